// round 10
// baseline (speedup 1.0000x reference)
#include <cuda_runtime.h>
#include <cstdint>

#define NPTS  40960
#define BATCH 4
#define KNN   16
#define DCH   64
#define HCH   32

// scratch: f = relu(bn(W2 @ feature))  -> [B*N][H]
__device__ float f_buf[(size_t)BATCH * NPTS * HCH];
__device__ int   g_is64;

__device__ __forceinline__ uint32_t to_tf32(float x) {
    uint32_t r;
    asm("cvt.rna.tf32.f32 %0, %1;" : "=r"(r) : "f"(x));
    return r;
}
__device__ __forceinline__ void mma_tf32(float c[4], uint32_t a0, uint32_t a1,
                                         uint32_t a2, uint32_t a3,
                                         uint32_t b0, uint32_t b1) {
    asm volatile(
        "mma.sync.aligned.m16n8k8.row.col.f32.tf32.tf32.f32 "
        "{%0,%1,%2,%3}, {%4,%5,%6,%7}, {%8,%9}, {%0,%1,%2,%3};"
        : "+f"(c[0]), "+f"(c[1]), "+f"(c[2]), "+f"(c[3])
        : "r"(a0), "r"(a1), "r"(a2), "r"(a3), "r"(b0), "r"(b1));
}

// ---------------------------------------------------------------------------
// conv2: tile of 128 points per block; also detects idx kind (block 0).
// ---------------------------------------------------------------------------
__global__ void __launch_bounds__(256, 4) conv2_kernel(
    const float* __restrict__ feature,
    const float* __restrict__ W2,
    const float* __restrict__ g2,
    const float* __restrict__ b2,
    const void*  __restrict__ nidx)
{
    __shared__ __align__(16) float Fs[DCH * 128];
    __shared__ float W2t[DCH * HCH];

    int tid = threadIdx.x;

    if (blockIdx.x == 0 && tid < 32) {
        const long long* p = (const long long*)nidx;
        int cnt = 0;
        #pragma unroll
        for (int i = 0; i < 8; i++) {
            long long v = p[tid + 32 * i];
            if (v >= 0 && v < NPTS) cnt++;
        }
        #pragma unroll
        for (int o = 16; o; o >>= 1) cnt += __shfl_down_sync(0xffffffffu, cnt, o);
        if (tid == 0) g_is64 = (cnt > 128) ? 1 : 0;
    }

    for (int i = tid; i < DCH * HCH; i += 256) {
        int d = i >> 5, h = i & 31;
        W2t[i] = W2[h * DCH + d];
    }
    int pg0 = blockIdx.x * 128;
    int b = pg0 / NPTS, n0 = pg0 % NPTS;
    const float4* fv = (const float4*)(feature + ((size_t)b * DCH) * NPTS + n0);
    for (int i = tid; i < DCH * 32; i += 256) {
        int d = i >> 5, q = i & 31;
        ((float4*)Fs)[d * 32 + q] = __ldg(fv + (size_t)d * (NPTS / 4) + q);
    }
    __syncthreads();

    int tx = tid & 15, ty = tid >> 4;
    float acc[8][2];
    #pragma unroll
    for (int i = 0; i < 8; i++) { acc[i][0] = 0.f; acc[i][1] = 0.f; }

    #pragma unroll 4
    for (int d = 0; d < DCH; d++) {
        float w0 = W2t[d * HCH + tx];
        float w1 = W2t[d * HCH + tx + 16];
        #pragma unroll
        for (int i = 0; i < 8; i++) {
            float a = Fs[d * 128 + ty + 16 * i];
            acc[i][0] = fmaf(a, w0, acc[i][0]);
            acc[i][1] = fmaf(a, w1, acc[i][1]);
        }
    }

    const float RS = rsqrtf(1.00001f);
    float s0 = __ldg(g2 + tx) * RS,      bb0 = __ldg(b2 + tx);
    float s1 = __ldg(g2 + tx + 16) * RS, bb1 = __ldg(b2 + tx + 16);
    float* fb = f_buf + (size_t)pg0 * HCH;
    #pragma unroll
    for (int i = 0; i < 8; i++) {
        int n_loc = ty + 16 * i;
        fb[(size_t)n_loc * HCH + tx]      = fmaxf(fmaf(acc[i][0], s0, bb0), 0.f);
        fb[(size_t)n_loc * HCH + tx + 16] = fmaxf(fmaf(acc[i][1], s1, bb1), 0.f);
    }
}

// ---------------------------------------------------------------------------
// Main fused kernel: 8 points/CTA.
// Phase A: gather + conv1 -> tf32 A tile [128][68] (pad-68, conflict-free)
// Phase B: per-warp mma.sync.m16n8k8.tf32, C[16x32] in registers
// Epilogue: in-register row-max (16 neighbors) + shfl reduce + BN/ReLU -> M2
// Phase C: conv4 (2 warps, W4 staged into retired A region) -> coalesced out
// ---------------------------------------------------------------------------
__global__ void __launch_bounds__(256) main_kernel(
    const float* __restrict__ xyz,
    const void*  __restrict__ nidx,
    const float* __restrict__ W1, const float* __restrict__ g1, const float* __restrict__ b1,
    const float* __restrict__ W3, const float* __restrict__ g3, const float* __restrict__ b3,
    const float* __restrict__ W4, const float* __restrict__ g4, const float* __restrict__ b4,
    float* __restrict__ out)
{
    __shared__ __align__(16) uint32_t As[128 * 68];   // 34816B; reused as W4t after MMA
    __shared__ __align__(16) uint32_t W3s[32 * 68];   // 8704B
    __shared__ __align__(16) float M2[8 * 64];        // 2048B
    __shared__ float Os[64 * 9];                      // 2304B
    __shared__ float s3s[32], b3s[32];

    int tid = threadIdx.x;
    int warp = tid >> 5, lane = tid & 31;

    const float RS = rsqrtf(1.00001f);
    if (tid < 32) {
        s3s[tid] = __ldg(g3 + tid) * RS;
        b3s[tid] = __ldg(b3 + tid);
    }
    // stage W3 (tf32): W3s[h][k], pad 68
    for (int i = tid; i < 2048; i += 256) {
        int h = i >> 6, c = i & 63;
        W3s[h * 68 + c] = to_tf32(__ldg(W3 + i));
    }

    int pg = blockIdx.x * 8 + warp;
    int b = pg / NPTS, n = pg % NPTS;
    int n0 = (blockIdx.x * 8) % NPTS;
    int b0 = (blockIdx.x * 8) / NPTS;

    const float* xb  = xyz + (size_t)b * NPTS * 3;
    const float* fbb = f_buf + (size_t)b * NPTS * HCH;

    // ---- Phase A ----
    {
        int jv = 0;
        if (lane < KNN) {
            size_t off = (size_t)(b * NPTS + n) * KNN;
            jv = g_is64 ? (int)((const long long*)nidx)[off + lane]
                        : ((const int*)nidx)[off + lane];
        }
        float nxv = 0.f, nyv = 0.f, nzv = 0.f;
        if (lane < KNN) {
            nxv = __ldg(xb + jv * 3 + 0);
            nyv = __ldg(xb + jv * 3 + 1);
            nzv = __ldg(xb + jv * 3 + 2);
        }

        float fnr[KNN];
        #pragma unroll
        for (int k = 0; k < KNN; k++) {
            int j = __shfl_sync(0xffffffffu, jv, k);
            fnr[k] = fbb[(size_t)j * HCH + lane];
        }

        float s1v = __ldg(g1 + lane) * RS, b1v = __ldg(b1 + lane);
        float w0 = __ldg(W1 + lane * 10 + 0);
        float w1 = __ldg(W1 + lane * 10 + 1), w2 = __ldg(W1 + lane * 10 + 2), w3 = __ldg(W1 + lane * 10 + 3);
        float w4 = __ldg(W1 + lane * 10 + 4), w5 = __ldg(W1 + lane * 10 + 5), w6 = __ldg(W1 + lane * 10 + 6);
        float w7 = __ldg(W1 + lane * 10 + 7), w8 = __ldg(W1 + lane * 10 + 8), w9 = __ldg(W1 + lane * 10 + 9);

        float cx = __ldg(xb + n * 3 + 0);
        float cy = __ldg(xb + n * 3 + 1);
        float cz = __ldg(xb + n * 3 + 2);

        float cterm = (w1 + w4) * cx + (w2 + w5) * cy + (w3 + w6) * cz;
        float qx = w7 - w1, qy = w8 - w2, qz = w9 - w3;

        #pragma unroll
        for (int k = 0; k < KNN; k++) {
            float px = __shfl_sync(0xffffffffu, nxv, k);
            float py = __shfl_sync(0xffffffffu, nyv, k);
            float pz = __shfl_sync(0xffffffffu, nzv, k);
            float rx = cx - px, ry = cy - py, rz = cz - pz;
            float dist = sqrtf(fmaf(rz, rz, fmaf(ry, ry, rx * rx)));
            float dot = fmaf(w0, dist, cterm);
            dot = fmaf(qx, px, dot);
            dot = fmaf(qy, py, dot);
            dot = fmaf(qz, pz, dot);
            float fx = fmaxf(fmaf(dot, s1v, b1v), 0.f);
            uint32_t base = (warp * 16 + k) * 68;
            As[base + lane]      = to_tf32(fnr[k]);
            As[base + 32 + lane] = to_tf32(fx);
        }
    }
    __syncthreads();

    // ---- Phase B: per-warp mma.sync tf32, C[16x32] = A[16x64] * W3^T ----
    int gid = lane >> 2, ltid = lane & 3;
    float c[4][4];
    #pragma unroll
    for (int j = 0; j < 4; j++)
        { c[j][0] = 0.f; c[j][1] = 0.f; c[j][2] = 0.f; c[j][3] = 0.f; }

    const uint32_t* Aw = As + (warp * 16) * 68;
    #pragma unroll
    for (int ks = 0; ks < 8; ks++) {
        int k0 = ks * 8;
        uint32_t a0 = Aw[gid * 68 + k0 + ltid];
        uint32_t a1 = Aw[(gid + 8) * 68 + k0 + ltid];
        uint32_t a2 = Aw[gid * 68 + k0 + ltid + 4];
        uint32_t a3 = Aw[(gid + 8) * 68 + k0 + ltid + 4];
        #pragma unroll
        for (int j = 0; j < 4; j++) {
            uint32_t b0 = W3s[(8 * j + gid) * 68 + k0 + ltid];
            uint32_t b1 = W3s[(8 * j + gid) * 68 + k0 + ltid + 4];
            mma_tf32(c[j], a0, a1, a2, a3, b0, b1);
        }
    }

    // ---- Epilogue: max over 16 rows (neighbors), BN+ReLU, write M2 ----
    #pragma unroll
    for (int j = 0; j < 4; j++) {
        float m0 = fmaxf(c[j][0], c[j][2]);
        float m1 = fmaxf(c[j][1], c[j][3]);
        #pragma unroll
        for (int o = 4; o <= 16; o <<= 1) {
            m0 = fmaxf(m0, __shfl_xor_sync(0xffffffffu, m0, o));
            m1 = fmaxf(m1, __shfl_xor_sync(0xffffffffu, m1, o));
        }
        if (gid == 0) {
            int nn = 8 * j + 2 * ltid;
            M2[warp * 64 + nn]     = fmaxf(fmaf(m0, s3s[nn],     b3s[nn]),     0.f);
            M2[warp * 64 + nn + 1] = fmaxf(fmaf(m1, s3s[nn + 1], b3s[nn + 1]), 0.f);
        }
    }
    // center features -> M2[warp][32+lane]
    M2[warp * 64 + 32 + lane] = fbb[(size_t)n * HCH + lane];
    __syncthreads();

    // ---- stage W4 transposed into retired A region: W4t[c][d] ----
    float* W4t = (float*)As;
    for (int i = tid; i < 1024; i += 256) {
        int d = i & 63, c4 = i >> 6;
        float4 wv = __ldg((const float4*)(W4 + d * 64) + c4);
        W4t[(4 * c4 + 0) * 64 + d] = wv.x;
        W4t[(4 * c4 + 1) * 64 + d] = wv.y;
        W4t[(4 * c4 + 2) * 64 + d] = wv.z;
        W4t[(4 * c4 + 3) * 64 + d] = wv.w;
    }
    __syncthreads();

    // ---- conv4 by warps 0,1: d = lane + 32*warp, loop 8 points ----
    if (warp < 2) {
        int d = lane + 32 * warp;
        float a4[8];
        #pragma unroll
        for (int pp = 0; pp < 8; pp++) a4[pp] = 0.f;
        const float4* M2v = (const float4*)M2;   // [p][16 float4]
        #pragma unroll 4
        for (int cc = 0; cc < 16; cc++) {
            float w0 = W4t[(4 * cc + 0) * 64 + d];
            float w1 = W4t[(4 * cc + 1) * 64 + d];
            float w2 = W4t[(4 * cc + 2) * 64 + d];
            float w3 = W4t[(4 * cc + 3) * 64 + d];
            #pragma unroll
            for (int pp = 0; pp < 8; pp++) {
                float4 mv = M2v[pp * 16 + cc];
                a4[pp] = fmaf(w0, mv.x, a4[pp]);
                a4[pp] = fmaf(w1, mv.y, a4[pp]);
                a4[pp] = fmaf(w2, mv.z, a4[pp]);
                a4[pp] = fmaf(w3, mv.w, a4[pp]);
            }
        }
        float s4 = __ldg(g4 + d) * RS, b4v = __ldg(b4 + d);
        #pragma unroll
        for (int pp = 0; pp < 8; pp++)
            Os[d * 9 + pp] = fmaxf(fmaf(a4[pp], s4, b4v), 0.f);
    }
    __syncthreads();

    // ---- coalesced output ----
    {
        int d = tid >> 2, pq = tid & 3;
        float2 v;
        v.x = Os[d * 9 + 2 * pq];
        v.y = Os[d * 9 + 2 * pq + 1];
        *(float2*)(out + ((size_t)b0 * DCH + d) * NPTS + n0 + 2 * pq) = v;
    }
}

// ---------------------------------------------------------------------------
extern "C" void kernel_launch(void* const* d_in, const int* in_sizes, int n_in,
                              void* d_out, int out_size)
{
    const float *feature, *xyz, *W1, *W2, *W3, *W4;
    const float *g1, *b1, *g2, *b2, *g3, *b3, *g4, *b4;
    const void* nidx;

    if (in_sizes[2] == BATCH * NPTS * KNN) {
        feature = (const float*)d_in[0];
        xyz     = (const float*)d_in[1];
        nidx    = d_in[2];
        W1 = (const float*)d_in[3];  W2 = (const float*)d_in[4];
        W3 = (const float*)d_in[5];  W4 = (const float*)d_in[6];
        g1 = (const float*)d_in[7];  b1 = (const float*)d_in[8];
        g2 = (const float*)d_in[9];  b2 = (const float*)d_in[10];
        g3 = (const float*)d_in[11]; b3 = (const float*)d_in[12];
        g4 = (const float*)d_in[13]; b4 = (const float*)d_in[14];
    } else {
        feature = (const float*)d_in[0];
        xyz     = (const float*)d_in[1];
        W1 = (const float*)d_in[2];  g1 = (const float*)d_in[3];  b1 = (const float*)d_in[4];
        W2 = (const float*)d_in[5];  g2 = (const float*)d_in[6];  b2 = (const float*)d_in[7];
        W3 = (const float*)d_in[8];  g3 = (const float*)d_in[9];  b3 = (const float*)d_in[10];
        W4 = (const float*)d_in[11]; g4 = (const float*)d_in[12]; b4 = (const float*)d_in[13];
        nidx = d_in[14];
    }

    conv2_kernel<<<BATCH * NPTS / 128, 256>>>(feature, W2, g2, b2, nidx);
    main_kernel<<<BATCH * NPTS / 8, 256>>>(xyz, nidx,
                                           W1, g1, b1, W3, g3, b3, W4, g4, b4,
                                           (float*)d_out);
}

// round 11
// speedup vs baseline: 1.4225x; 1.4225x over previous
#include <cuda_runtime.h>
#include <cstdint>

#define NPTS  40960
#define BATCH 4
#define KNN   16
#define DCH   64
#define HCH   32

// scratch: f = relu(bn(W2 @ feature))  -> [B*N][H]
__device__ float f_buf[(size_t)BATCH * NPTS * HCH];
__device__ int   g_is64;

__device__ __forceinline__ uint32_t to_tf32(float x) {
    uint32_t r;
    asm("cvt.rna.tf32.f32 %0, %1;" : "=r"(r) : "f"(x));
    return r;
}
__device__ __forceinline__ void mma_tf32(float c[4], uint32_t a0, uint32_t a1,
                                         uint32_t a2, uint32_t a3,
                                         uint32_t b0, uint32_t b1) {
    asm volatile(
        "mma.sync.aligned.m16n8k8.row.col.f32.tf32.tf32.f32 "
        "{%0,%1,%2,%3}, {%4,%5,%6,%7}, {%8,%9}, {%0,%1,%2,%3};"
        : "+f"(c[0]), "+f"(c[1]), "+f"(c[2]), "+f"(c[3])
        : "r"(a0), "r"(a1), "r"(a2), "r"(a3), "r"(b0), "r"(b1));
}
// K-permutation within each 8-col octet: [c0,c4,c1,c5,c2,c6,c3,c7]
// -> fragment pairs (ltid, ltid+4) are adjacent => LDS.64 loads.
__device__ __forceinline__ int permc(int c) {
    return (c & ~7) | ((c & 3) << 1) | ((c >> 2) & 1);
}

// ---------------------------------------------------------------------------
// conv2: tile of 128 points per block; also detects idx kind (block 0).
// ---------------------------------------------------------------------------
__global__ void __launch_bounds__(256, 4) conv2_kernel(
    const float* __restrict__ feature,
    const float* __restrict__ W2,
    const float* __restrict__ g2,
    const float* __restrict__ b2,
    const void*  __restrict__ nidx)
{
    __shared__ __align__(16) float Fs[DCH * 128];
    __shared__ float W2t[DCH * HCH];

    int tid = threadIdx.x;

    if (blockIdx.x == 0 && tid < 32) {
        const long long* p = (const long long*)nidx;
        int cnt = 0;
        #pragma unroll
        for (int i = 0; i < 8; i++) {
            long long v = p[tid + 32 * i];
            if (v >= 0 && v < NPTS) cnt++;
        }
        #pragma unroll
        for (int o = 16; o; o >>= 1) cnt += __shfl_down_sync(0xffffffffu, cnt, o);
        if (tid == 0) g_is64 = (cnt > 128) ? 1 : 0;
    }

    for (int i = tid; i < DCH * HCH; i += 256) {
        int d = i >> 5, h = i & 31;
        W2t[i] = W2[h * DCH + d];
    }
    int pg0 = blockIdx.x * 128;
    int b = pg0 / NPTS, n0 = pg0 % NPTS;
    const float4* fv = (const float4*)(feature + ((size_t)b * DCH) * NPTS + n0);
    for (int i = tid; i < DCH * 32; i += 256) {
        int d = i >> 5, q = i & 31;
        ((float4*)Fs)[d * 32 + q] = __ldg(fv + (size_t)d * (NPTS / 4) + q);
    }
    __syncthreads();

    int tx = tid & 15, ty = tid >> 4;
    float acc[8][2];
    #pragma unroll
    for (int i = 0; i < 8; i++) { acc[i][0] = 0.f; acc[i][1] = 0.f; }

    #pragma unroll 4
    for (int d = 0; d < DCH; d++) {
        float w0 = W2t[d * HCH + tx];
        float w1 = W2t[d * HCH + tx + 16];
        #pragma unroll
        for (int i = 0; i < 8; i++) {
            float a = Fs[d * 128 + ty + 16 * i];
            acc[i][0] = fmaf(a, w0, acc[i][0]);
            acc[i][1] = fmaf(a, w1, acc[i][1]);
        }
    }

    const float RS = rsqrtf(1.00001f);
    float s0 = __ldg(g2 + tx) * RS,      bb0 = __ldg(b2 + tx);
    float s1 = __ldg(g2 + tx + 16) * RS, bb1 = __ldg(b2 + tx + 16);
    float* fb = f_buf + (size_t)pg0 * HCH;
    #pragma unroll
    for (int i = 0; i < 8; i++) {
        int n_loc = ty + 16 * i;
        fb[(size_t)n_loc * HCH + tx]      = fmaxf(fmaf(acc[i][0], s0, bb0), 0.f);
        fb[(size_t)n_loc * HCH + tx + 16] = fmaxf(fmaf(acc[i][1], s1, bb1), 0.f);
    }
}

// ---------------------------------------------------------------------------
// Main fused kernel: 8 points/CTA, 4 CTAs/SM.
// Phase A: gather + conv1 -> tf32 A tile [128][68], K-permuted octets
// Phase B: per-warp mma.sync.m16n8k8.tf32 with LDS.64 fragment loads
// Epilogue: in-register row-max + shfl reduce + BN/ReLU -> M2
// Phase C: conv4 (4 warps) -> coalesced out
// ---------------------------------------------------------------------------
__global__ void __launch_bounds__(256, 4) main_kernel(
    const float* __restrict__ xyz,
    const void*  __restrict__ nidx,
    const float* __restrict__ W1, const float* __restrict__ g1, const float* __restrict__ b1,
    const float* __restrict__ W3, const float* __restrict__ g3, const float* __restrict__ b3,
    const float* __restrict__ W4, const float* __restrict__ g4, const float* __restrict__ b4,
    float* __restrict__ out)
{
    __shared__ __align__(16) uint32_t As[128 * 68];   // 34816B; reused as W4t after MMA
    __shared__ __align__(16) uint32_t W3s[32 * 68];   // 8704B
    __shared__ __align__(16) float M2[8 * 64];        // 2048B
    __shared__ float Os[64 * 9];                      // 2304B
    __shared__ float s3s[32], b3s[32];

    int tid = threadIdx.x;
    int warp = tid >> 5, lane = tid & 31;

    const float RS = rsqrtf(1.00001f);
    if (tid < 32) {
        s3s[tid] = __ldg(g3 + tid) * RS;
        b3s[tid] = __ldg(b3 + tid);
    }
    // stage W3 (tf32, K-permuted): W3s[h][permc(k)]
    for (int i = tid; i < 2048; i += 256) {
        int h = i >> 6, c = i & 63;
        W3s[h * 68 + permc(c)] = to_tf32(__ldg(W3 + i));
    }

    int pg = blockIdx.x * 8 + warp;
    int b = pg / NPTS, n = pg % NPTS;
    int n0 = (blockIdx.x * 8) % NPTS;
    int b0 = (blockIdx.x * 8) / NPTS;

    const float* xb  = xyz + (size_t)b * NPTS * 3;
    const float* fbb = f_buf + (size_t)b * NPTS * HCH;

    // ---- Phase A ----
    {
        int jv = 0;
        if (lane < KNN) {
            size_t off = (size_t)(b * NPTS + n) * KNN;
            jv = g_is64 ? (int)((const long long*)nidx)[off + lane]
                        : ((const int*)nidx)[off + lane];
        }
        float nxv = 0.f, nyv = 0.f, nzv = 0.f;
        if (lane < KNN) {
            nxv = __ldg(xb + jv * 3 + 0);
            nyv = __ldg(xb + jv * 3 + 1);
            nzv = __ldg(xb + jv * 3 + 2);
        }

        float fnr[KNN];
        #pragma unroll
        for (int k = 0; k < KNN; k++) {
            int j = __shfl_sync(0xffffffffu, jv, k);
            fnr[k] = fbb[(size_t)j * HCH + lane];
        }

        float s1v = __ldg(g1 + lane) * RS, b1v = __ldg(b1 + lane);
        float w0 = __ldg(W1 + lane * 10 + 0);
        float w1 = __ldg(W1 + lane * 10 + 1), w2 = __ldg(W1 + lane * 10 + 2), w3 = __ldg(W1 + lane * 10 + 3);
        float w4 = __ldg(W1 + lane * 10 + 4), w5 = __ldg(W1 + lane * 10 + 5), w6 = __ldg(W1 + lane * 10 + 6);
        float w7 = __ldg(W1 + lane * 10 + 7), w8 = __ldg(W1 + lane * 10 + 8), w9 = __ldg(W1 + lane * 10 + 9);

        float cx = __ldg(xb + n * 3 + 0);
        float cy = __ldg(xb + n * 3 + 1);
        float cz = __ldg(xb + n * 3 + 2);

        float cterm = (w1 + w4) * cx + (w2 + w5) * cy + (w3 + w6) * cz;
        float qx = w7 - w1, qy = w8 - w2, qz = w9 - w3;

        int pcA = permc(lane);        // column for neighbor feature
        int pcB = permc(32 + lane);   // column for conv1 output
        #pragma unroll
        for (int k = 0; k < KNN; k++) {
            float px = __shfl_sync(0xffffffffu, nxv, k);
            float py = __shfl_sync(0xffffffffu, nyv, k);
            float pz = __shfl_sync(0xffffffffu, nzv, k);
            float rx = cx - px, ry = cy - py, rz = cz - pz;
            float dist = sqrtf(fmaf(rz, rz, fmaf(ry, ry, rx * rx)));
            float dot = fmaf(w0, dist, cterm);
            dot = fmaf(qx, px, dot);
            dot = fmaf(qy, py, dot);
            dot = fmaf(qz, pz, dot);
            float fx = fmaxf(fmaf(dot, s1v, b1v), 0.f);
            uint32_t base = (warp * 16 + k) * 68;
            As[base + pcA] = to_tf32(fnr[k]);
            As[base + pcB] = to_tf32(fx);
        }
    }
    __syncthreads();

    // ---- Phase B: per-warp mma.sync tf32, C[16x32] = A[16x64] * W3^T ----
    int gid = lane >> 2, ltid = lane & 3;
    float c[4][4];
    #pragma unroll
    for (int j = 0; j < 4; j++)
        { c[j][0] = 0.f; c[j][1] = 0.f; c[j][2] = 0.f; c[j][3] = 0.f; }

    const uint32_t* ArowA = As + (warp * 16 + gid) * 68 + 2 * ltid;
    const uint32_t* ArowB = ArowA + 8 * 68;
    const uint32_t* Wrow  = W3s + gid * 68 + 2 * ltid;

    #pragma unroll
    for (int ks = 0; ks < 8; ks++) {
        int k0 = ks * 8;
        uint2 aA = *(const uint2*)(ArowA + k0);   // a0 = A[gid][k+ltid], a2 = +4
        uint2 aB = *(const uint2*)(ArowB + k0);   // a1, a3
        #pragma unroll
        for (int j = 0; j < 4; j++) {
            uint2 bb = *(const uint2*)(Wrow + j * 8 * 68 + k0);   // b0, b1
            mma_tf32(c[j], aA.x, aB.x, aA.y, aB.y, bb.x, bb.y);
        }
    }

    // ---- Epilogue: max over 16 rows (neighbors), BN+ReLU, write M2 ----
    #pragma unroll
    for (int j = 0; j < 4; j++) {
        float m0 = fmaxf(c[j][0], c[j][2]);
        float m1 = fmaxf(c[j][1], c[j][3]);
        #pragma unroll
        for (int o = 4; o <= 16; o <<= 1) {
            m0 = fmaxf(m0, __shfl_xor_sync(0xffffffffu, m0, o));
            m1 = fmaxf(m1, __shfl_xor_sync(0xffffffffu, m1, o));
        }
        if (gid == 0) {
            int nn = 8 * j + 2 * ltid;
            M2[warp * 64 + nn]     = fmaxf(fmaf(m0, s3s[nn],     b3s[nn]),     0.f);
            M2[warp * 64 + nn + 1] = fmaxf(fmaf(m1, s3s[nn + 1], b3s[nn + 1]), 0.f);
        }
    }
    // center features -> M2[warp][32+lane]
    M2[warp * 64 + 32 + lane] = fbb[(size_t)n * HCH + lane];
    __syncthreads();

    // ---- stage W4 transposed into retired A region: W4t[c][d] ----
    float* W4t = (float*)As;
    for (int i = tid; i < 1024; i += 256) {
        int d = i & 63, c4 = i >> 6;
        float4 wv = __ldg((const float4*)(W4 + d * 64) + c4);
        W4t[(4 * c4 + 0) * 64 + d] = wv.x;
        W4t[(4 * c4 + 1) * 64 + d] = wv.y;
        W4t[(4 * c4 + 2) * 64 + d] = wv.z;
        W4t[(4 * c4 + 3) * 64 + d] = wv.w;
    }
    __syncthreads();

    // ---- conv4 by warps 0..3: d = lane + 32*(warp&1), 4 points each ----
    if (warp < 4) {
        int d = lane + 32 * (warp & 1);
        int p0 = (warp >> 1) * 4;
        float a4[4];
        #pragma unroll
        for (int pp = 0; pp < 4; pp++) a4[pp] = 0.f;
        const float4* M2v = (const float4*)M2 + p0 * 16;   // [4 points][16 float4]
        #pragma unroll 4
        for (int cc = 0; cc < 16; cc++) {
            float w0 = W4t[(4 * cc + 0) * 64 + d];
            float w1 = W4t[(4 * cc + 1) * 64 + d];
            float w2 = W4t[(4 * cc + 2) * 64 + d];
            float w3 = W4t[(4 * cc + 3) * 64 + d];
            #pragma unroll
            for (int pp = 0; pp < 4; pp++) {
                float4 mv = M2v[pp * 16 + cc];
                a4[pp] = fmaf(w0, mv.x, a4[pp]);
                a4[pp] = fmaf(w1, mv.y, a4[pp]);
                a4[pp] = fmaf(w2, mv.z, a4[pp]);
                a4[pp] = fmaf(w3, mv.w, a4[pp]);
            }
        }
        float s4 = __ldg(g4 + d) * RS, b4v = __ldg(b4 + d);
        #pragma unroll
        for (int pp = 0; pp < 4; pp++)
            Os[d * 9 + p0 + pp] = fmaxf(fmaf(a4[pp], s4, b4v), 0.f);
    }
    __syncthreads();

    // ---- coalesced output ----
    {
        int d = tid >> 2, pq = tid & 3;
        float2 v;
        v.x = Os[d * 9 + 2 * pq];
        v.y = Os[d * 9 + 2 * pq + 1];
        *(float2*)(out + ((size_t)b0 * DCH + d) * NPTS + n0 + 2 * pq) = v;
    }
}

// ---------------------------------------------------------------------------
extern "C" void kernel_launch(void* const* d_in, const int* in_sizes, int n_in,
                              void* d_out, int out_size)
{
    const float *feature, *xyz, *W1, *W2, *W3, *W4;
    const float *g1, *b1, *g2, *b2, *g3, *b3, *g4, *b4;
    const void* nidx;

    if (in_sizes[2] == BATCH * NPTS * KNN) {
        feature = (const float*)d_in[0];
        xyz     = (const float*)d_in[1];
        nidx    = d_in[2];
        W1 = (const float*)d_in[3];  W2 = (const float*)d_in[4];
        W3 = (const float*)d_in[5];  W4 = (const float*)d_in[6];
        g1 = (const float*)d_in[7];  b1 = (const float*)d_in[8];
        g2 = (const float*)d_in[9];  b2 = (const float*)d_in[10];
        g3 = (const float*)d_in[11]; b3 = (const float*)d_in[12];
        g4 = (const float*)d_in[13]; b4 = (const float*)d_in[14];
    } else {
        feature = (const float*)d_in[0];
        xyz     = (const float*)d_in[1];
        W1 = (const float*)d_in[2];  g1 = (const float*)d_in[3];  b1 = (const float*)d_in[4];
        W2 = (const float*)d_in[5];  g2 = (const float*)d_in[6];  b2 = (const float*)d_in[7];
        W3 = (const float*)d_in[8];  g3 = (const float*)d_in[9];  b3 = (const float*)d_in[10];
        W4 = (const float*)d_in[11]; g4 = (const float*)d_in[12]; b4 = (const float*)d_in[13];
        nidx = d_in[14];
    }

    conv2_kernel<<<BATCH * NPTS / 128, 256>>>(feature, W2, g2, b2, nidx);
    main_kernel<<<BATCH * NPTS / 8, 256>>>(xyz, nidx,
                                           W1, g1, b1, W3, g3, b3, W4, g4, b4,
                                           (float*)d_out);
}

// round 12
// speedup vs baseline: 1.4358x; 1.0093x over previous
#include <cuda_runtime.h>
#include <cstdint>

#define NPTS  40960
#define BATCH 4
#define KNN   16
#define DCH   64
#define HCH   32

// scratch: f = relu(bn(W2 @ feature))  -> [B*N][H]
__device__ float f_buf[(size_t)BATCH * NPTS * HCH];
__device__ int   g_is64;

__device__ __forceinline__ void mma_tf32(float c[4], uint32_t a0, uint32_t a1,
                                         uint32_t a2, uint32_t a3,
                                         uint32_t b0, uint32_t b1) {
    asm volatile(
        "mma.sync.aligned.m16n8k8.row.col.f32.tf32.tf32.f32 "
        "{%0,%1,%2,%3}, {%4,%5,%6,%7}, {%8,%9}, {%0,%1,%2,%3};"
        : "+f"(c[0]), "+f"(c[1]), "+f"(c[2]), "+f"(c[3])
        : "r"(a0), "r"(a1), "r"(a2), "r"(a3), "r"(b0), "r"(b1));
}
// permutation within an 8-col octet: mem pos of logical col x
__device__ __forceinline__ int pm8(int x) { return ((x & 3) << 1) | ((x >> 2) & 1); }
__device__ __forceinline__ int P4(int c)  { return (c & ~7) | pm8(c & 7); }

// ---------------------------------------------------------------------------
// conv2: tile of 128 points per block; also detects idx kind (block 0).
// ---------------------------------------------------------------------------
__global__ void __launch_bounds__(256, 4) conv2_kernel(
    const float* __restrict__ feature,
    const float* __restrict__ W2,
    const float* __restrict__ g2,
    const float* __restrict__ b2,
    const void*  __restrict__ nidx)
{
    __shared__ __align__(16) float Fs[DCH * 128];
    __shared__ float W2t[DCH * HCH];

    int tid = threadIdx.x;

    if (blockIdx.x == 0 && tid < 32) {
        const long long* p = (const long long*)nidx;
        int cnt = 0;
        #pragma unroll
        for (int i = 0; i < 8; i++) {
            long long v = p[tid + 32 * i];
            if (v >= 0 && v < NPTS) cnt++;
        }
        #pragma unroll
        for (int o = 16; o; o >>= 1) cnt += __shfl_down_sync(0xffffffffu, cnt, o);
        if (tid == 0) g_is64 = (cnt > 128) ? 1 : 0;
    }

    for (int i = tid; i < DCH * HCH; i += 256) {
        int d = i >> 5, h = i & 31;
        W2t[i] = W2[h * DCH + d];
    }
    int pg0 = blockIdx.x * 128;
    int b = pg0 / NPTS, n0 = pg0 % NPTS;
    const float4* fv = (const float4*)(feature + ((size_t)b * DCH) * NPTS + n0);
    for (int i = tid; i < DCH * 32; i += 256) {
        int d = i >> 5, q = i & 31;
        ((float4*)Fs)[d * 32 + q] = __ldg(fv + (size_t)d * (NPTS / 4) + q);
    }
    __syncthreads();

    int tx = tid & 15, ty = tid >> 4;
    float acc[8][2];
    #pragma unroll
    for (int i = 0; i < 8; i++) { acc[i][0] = 0.f; acc[i][1] = 0.f; }

    #pragma unroll 4
    for (int d = 0; d < DCH; d++) {
        float w0 = W2t[d * HCH + tx];
        float w1 = W2t[d * HCH + tx + 16];
        #pragma unroll
        for (int i = 0; i < 8; i++) {
            float a = Fs[d * 128 + ty + 16 * i];
            acc[i][0] = fmaf(a, w0, acc[i][0]);
            acc[i][1] = fmaf(a, w1, acc[i][1]);
        }
    }

    const float RS = rsqrtf(1.00001f);
    float s0 = __ldg(g2 + tx) * RS,      bb0 = __ldg(b2 + tx);
    float s1 = __ldg(g2 + tx + 16) * RS, bb1 = __ldg(b2 + tx + 16);
    float* fb = f_buf + (size_t)pg0 * HCH;
    #pragma unroll
    for (int i = 0; i < 8; i++) {
        int n_loc = ty + 16 * i;
        fb[(size_t)n_loc * HCH + tx]      = fmaxf(fmaf(acc[i][0], s0, bb0), 0.f);
        fb[(size_t)n_loc * HCH + tx + 16] = fmaxf(fmaf(acc[i][1], s1, bb1), 0.f);
    }
}

// ---------------------------------------------------------------------------
// Main fused kernel: 8 points/CTA, 4 CTAs/SM.
// A tile [128][68]: cols 0-31 neighbor feats, 32-63 conv1 out, 48-63 also
// used early as the conv1 X input (overwritten after conv1 MMA).
// conv1 AND conv3 both run on mma.sync.m16n8k8.tf32.
// ---------------------------------------------------------------------------
__global__ void __launch_bounds__(256, 4) main_kernel(
    const float* __restrict__ xyz,
    const void*  __restrict__ nidx,
    const float* __restrict__ W1, const float* __restrict__ g1, const float* __restrict__ b1,
    const float* __restrict__ W3, const float* __restrict__ g3, const float* __restrict__ b3,
    const float* __restrict__ W4, const float* __restrict__ g4, const float* __restrict__ b4,
    float* __restrict__ out)
{
    __shared__ __align__(16) float As[128 * 68];   // 34816B; reused as W4t+Os later
    __shared__ __align__(16) float W3s[32 * 68];   // 8704B
    __shared__ __align__(16) float W1s[32 * 20];   // 2560B
    __shared__ __align__(16) float M2[8 * 64];     // 2048B
    __shared__ float s1s[32], b1s[32], s3s[32], b3s[32];

    float* W4t = As;            // [c][d] 16KB, staged after conv3
    float* Os  = As + 4096;     // [64][9] output staging, after W4t

    int tid = threadIdx.x;
    int warp = tid >> 5, lane = tid & 31;
    const float RS = rsqrtf(1.00001f);

    if (tid < 32) {
        s1s[tid] = __ldg(g1 + tid) * RS; b1s[tid] = __ldg(b1 + tid);
        s3s[tid] = __ldg(g3 + tid) * RS; b3s[tid] = __ldg(b3 + tid);
    }
    // stage W1 -> W1s[h][16 pad 20], octet-permuted, zero-padded K 10->16
    for (int i = tid; i < 512; i += 256) {
        int h = i >> 4, p = i & 15;
        int po = p & 7;
        int c = (p & 8) + ((po & 1) ? 4 : 0) + (po >> 1);   // logical col at mem p
        W1s[h * 20 + p] = (c < 10) ? __ldg(W1 + h * 10 + c) : 0.f;
    }
    // stage W3 -> W3s[h][P4(c)]
    for (int i = tid; i < 2048; i += 256) {
        int h = i >> 6, c = i & 63;
        W3s[h * 68 + P4(c)] = __ldg(W3 + i);
    }

    int pg = blockIdx.x * 8 + warp;
    int b = pg / NPTS, n = pg % NPTS;
    int n0 = (blockIdx.x * 8) % NPTS;
    int b0 = (blockIdx.x * 8) / NPTS;
    int R = warp * 16;

    const float* xb  = xyz + (size_t)b * NPTS * 3;
    const float* fbb = f_buf + (size_t)b * NPTS * HCH;

    // ---- Phase A: X rows (lanes 0-15) + vectorized fn gather ----
    int jv = 0;
    if (lane < KNN) {
        size_t off = (size_t)(b * NPTS + n) * KNN;
        jv = g_is64 ? (int)((const long long*)nidx)[off + lane]
                    : ((const int*)nidx)[off + lane];
    }
    float cx = __ldg(xb + n * 3 + 0);
    float cy = __ldg(xb + n * 3 + 1);
    float cz = __ldg(xb + n * 3 + 2);

    if (lane < KNN) {
        float px = __ldg(xb + jv * 3 + 0);
        float py = __ldg(xb + jv * 3 + 1);
        float pz = __ldg(xb + jv * 3 + 2);
        float rx = cx - px, ry = cy - py, rz = cz - pz;
        float dist = sqrtf(fmaf(rz, rz, fmaf(ry, ry, rx * rx)));
        // X vector: [dist,rx,ry,rz,cx,cy,cz,px,py,pz,0..0], stored pre-permuted
        float* Xr = As + (R + lane) * 68 + 48;
        *(float4*)(Xr + 0)  = make_float4(dist, cx, rx, cy);
        *(float4*)(Xr + 4)  = make_float4(ry, cz, rz, px);
        *(float4*)(Xr + 8)  = make_float4(py, 0.f, pz, 0.f);
        *(float4*)(Xr + 12) = make_float4(0.f, 0.f, 0.f, 0.f);
    }
    // fn gather: lane = 8*r + q handles row k=g*4+r, cols 4q..4q+3
    {
        int r = lane >> 3, q = lane & 7;
        int cbase = ((q >> 1) << 3) + (q & 1);   // P4(4q+i) = cbase + 2i
        #pragma unroll
        for (int g = 0; g < 4; g++) {
            int k = g * 4 + r;
            int j = __shfl_sync(0xffffffffu, jv, k);
            float4 v = *(const float4*)(fbb + (size_t)j * HCH + 4 * q);
            float* dst = As + (R + k) * 68 + cbase;
            dst[0] = v.x; dst[2] = v.y; dst[4] = v.z; dst[6] = v.w;
        }
    }
    __syncthreads();   // W1s/W3s staged + own-warp A writes visible

    int gid = lane >> 2, ltid = lane & 3;

    // ---- conv1 MMA: C1[16 k][32 h1] = X[16][16] * W1s^T ----
    {
        float c1[4][4];
        #pragma unroll
        for (int j = 0; j < 4; j++)
            { c1[j][0] = 0.f; c1[j][1] = 0.f; c1[j][2] = 0.f; c1[j][3] = 0.f; }

        const float* XA = As + (R + gid) * 68 + 48 + 2 * ltid;
        const float* XB = XA + 8 * 68;
        const float* Wr = W1s + gid * 20 + 2 * ltid;
        #pragma unroll
        for (int ks = 0; ks < 2; ks++) {
            uint2 aA = *(const uint2*)(XA + 8 * ks);
            uint2 aB = *(const uint2*)(XB + 8 * ks);
            #pragma unroll
            for (int j = 0; j < 4; j++) {
                uint2 bb = *(const uint2*)(Wr + j * 160 + 8 * ks);
                mma_tf32(c1[j], aA.x, aB.x, aA.y, aB.y, bb.x, bb.y);
            }
        }
        // epilogue: BN+ReLU, store into A cols 32-63 (octet-permuted)
        #pragma unroll
        for (int j = 0; j < 4; j++) {
            int h1 = 8 * j + 2 * ltid;
            float sA = s1s[h1], bA = b1s[h1];
            float sB = s1s[h1 + 1], bB = b1s[h1 + 1];
            int mA = 32 + 8 * j + pm8(2 * ltid);
            int mB = 32 + 8 * j + pm8(2 * ltid + 1);
            float* r0 = As + (R + gid) * 68;
            float* r1 = As + (R + gid + 8) * 68;
            r0[mA] = fmaxf(fmaf(c1[j][0], sA, bA), 0.f);
            r0[mB] = fmaxf(fmaf(c1[j][1], sB, bB), 0.f);
            r1[mA] = fmaxf(fmaf(c1[j][2], sA, bA), 0.f);
            r1[mB] = fmaxf(fmaf(c1[j][3], sB, bB), 0.f);
        }
    }
    __syncwarp();   // own-warp rows complete for conv3

    // ---- conv3 MMA: C[16 k][32 h3] = A[16][64] * W3s^T ----
    float c[4][4];
    #pragma unroll
    for (int j = 0; j < 4; j++)
        { c[j][0] = 0.f; c[j][1] = 0.f; c[j][2] = 0.f; c[j][3] = 0.f; }

    {
        const float* ArowA = As + (R + gid) * 68 + 2 * ltid;
        const float* ArowB = ArowA + 8 * 68;
        const float* Wrow  = W3s + gid * 68 + 2 * ltid;
        #pragma unroll
        for (int ks = 0; ks < 8; ks++) {
            uint2 aA = *(const uint2*)(ArowA + 8 * ks);
            uint2 aB = *(const uint2*)(ArowB + 8 * ks);
            #pragma unroll
            for (int j = 0; j < 4; j++) {
                uint2 bb = *(const uint2*)(Wrow + j * 544 + 8 * ks);
                mma_tf32(c[j], aA.x, aB.x, aA.y, aB.y, bb.x, bb.y);
            }
        }
    }

    // ---- epilogue: max over 16 neighbors, BN+ReLU -> M2 ----
    #pragma unroll
    for (int j = 0; j < 4; j++) {
        float m0 = fmaxf(c[j][0], c[j][2]);
        float m1 = fmaxf(c[j][1], c[j][3]);
        #pragma unroll
        for (int o = 4; o <= 16; o <<= 1) {
            m0 = fmaxf(m0, __shfl_xor_sync(0xffffffffu, m0, o));
            m1 = fmaxf(m1, __shfl_xor_sync(0xffffffffu, m1, o));
        }
        if (gid == 0) {
            int nn = 8 * j + 2 * ltid;
            M2[warp * 64 + nn]     = fmaxf(fmaf(m0, s3s[nn],     b3s[nn]),     0.f);
            M2[warp * 64 + nn + 1] = fmaxf(fmaf(m1, s3s[nn + 1], b3s[nn + 1]), 0.f);
        }
    }
    M2[warp * 64 + 32 + lane] = fbb[(size_t)n * HCH + lane];
    __syncthreads();   // all conv3 reads of As done

    // ---- stage W4 transposed into retired A region: W4t[c][d] ----
    for (int i = tid; i < 1024; i += 256) {
        int d = i & 63, c4 = i >> 6;
        float4 wv = __ldg((const float4*)(W4 + d * 64) + c4);
        W4t[(4 * c4 + 0) * 64 + d] = wv.x;
        W4t[(4 * c4 + 1) * 64 + d] = wv.y;
        W4t[(4 * c4 + 2) * 64 + d] = wv.z;
        W4t[(4 * c4 + 3) * 64 + d] = wv.w;
    }
    __syncthreads();

    // ---- conv4 by warps 0..3 ----
    if (warp < 4) {
        int d = lane + 32 * (warp & 1);
        int p0 = (warp >> 1) * 4;
        float a4[4];
        #pragma unroll
        for (int pp = 0; pp < 4; pp++) a4[pp] = 0.f;
        const float4* M2v = (const float4*)M2 + p0 * 16;
        #pragma unroll 4
        for (int cc = 0; cc < 16; cc++) {
            float w0 = W4t[(4 * cc + 0) * 64 + d];
            float w1 = W4t[(4 * cc + 1) * 64 + d];
            float w2 = W4t[(4 * cc + 2) * 64 + d];
            float w3 = W4t[(4 * cc + 3) * 64 + d];
            #pragma unroll
            for (int pp = 0; pp < 4; pp++) {
                float4 mv = M2v[pp * 16 + cc];
                a4[pp] = fmaf(w0, mv.x, a4[pp]);
                a4[pp] = fmaf(w1, mv.y, a4[pp]);
                a4[pp] = fmaf(w2, mv.z, a4[pp]);
                a4[pp] = fmaf(w3, mv.w, a4[pp]);
            }
        }
        float s4 = __ldg(g4 + d) * RS, b4v = __ldg(b4 + d);
        #pragma unroll
        for (int pp = 0; pp < 4; pp++)
            Os[d * 9 + p0 + pp] = fmaxf(fmaf(a4[pp], s4, b4v), 0.f);
    }
    __syncthreads();

    // ---- coalesced output ----
    {
        int d = tid >> 2, pq = tid & 3;
        float2 v;
        v.x = Os[d * 9 + 2 * pq];
        v.y = Os[d * 9 + 2 * pq + 1];
        *(float2*)(out + ((size_t)b0 * DCH + d) * NPTS + n0 + 2 * pq) = v;
    }
}

// ---------------------------------------------------------------------------
extern "C" void kernel_launch(void* const* d_in, const int* in_sizes, int n_in,
                              void* d_out, int out_size)
{
    const float *feature, *xyz, *W1, *W2, *W3, *W4;
    const float *g1, *b1, *g2, *b2, *g3, *b3, *g4, *b4;
    const void* nidx;

    if (in_sizes[2] == BATCH * NPTS * KNN) {
        feature = (const float*)d_in[0];
        xyz     = (const float*)d_in[1];
        nidx    = d_in[2];
        W1 = (const float*)d_in[3];  W2 = (const float*)d_in[4];
        W3 = (const float*)d_in[5];  W4 = (const float*)d_in[6];
        g1 = (const float*)d_in[7];  b1 = (const float*)d_in[8];
        g2 = (const float*)d_in[9];  b2 = (const float*)d_in[10];
        g3 = (const float*)d_in[11]; b3 = (const float*)d_in[12];
        g4 = (const float*)d_in[13]; b4 = (const float*)d_in[14];
    } else {
        feature = (const float*)d_in[0];
        xyz     = (const float*)d_in[1];
        W1 = (const float*)d_in[2];  g1 = (const float*)d_in[3];  b1 = (const float*)d_in[4];
        W2 = (const float*)d_in[5];  g2 = (const float*)d_in[6];  b2 = (const float*)d_in[7];
        W3 = (const float*)d_in[8];  g3 = (const float*)d_in[9];  b3 = (const float*)d_in[10];
        W4 = (const float*)d_in[11]; g4 = (const float*)d_in[12]; b4 = (const float*)d_in[13];
        nidx = d_in[14];
    }

    conv2_kernel<<<BATCH * NPTS / 128, 256>>>(feature, W2, g2, b2, nidx);
    main_kernel<<<BATCH * NPTS / 8, 256>>>(xyz, nidx,
                                           W1, g1, b1, W3, g3, b3, W4, g4, b4,
                                           (float*)d_out);
}